// round 16
// baseline (speedup 1.0000x reference)
#include <cuda_runtime.h>
#include <cuda_bf16.h>
#include <math.h>
#include <stdint.h>

typedef __nv_bfloat16 bf16;

#define BATCH   4
#define SEQ     501
#define BL      (BATCH*SEQ)     // 2004
#define NPOS    500
#define DM      256
#define DI      512
#define NLAYER  8

// ------------------------- scratch (device globals; no allocs) -------------------------
__device__ float g_h[BL*DM];
__device__ float g_xcres[BL*1024];
__device__ float g_xz[2L*BL*1024];
__device__ float g_u[2L*BL*DI];
__device__ float g_dbc[2L*BL*64];
__device__ float g_delta[2L*BL*DI];

__device__ bf16 g_xn_hi[BL*DM],    g_xn_lo[BL*DM];
__device__ bf16 g_xc_hi[BL*DI],    g_xc_lo[BL*DI];
__device__ bf16 g_u_hi[2L*BL*DI],  g_u_lo[2L*BL*DI];
__device__ bf16 g_dbc_hi[2L*BL*64],g_dbc_lo[2L*BL*64];
__device__ bf16 g_yg_hi[2L*BL*DI], g_yg_lo[2L*BL*DI];
__device__ bf16 g_cat_hi[BL*1024], g_cat_lo[BL*1024];

// preconverted-weight arena (bf16 hi/lo)
#define OFF_WIN   0L
#define OFF_MINF  (OFF_WIN  + 8L*1024*256)
#define OFF_MINB  (OFF_MINF + 8L*1024*512)
#define OFF_XPF   (OFF_MINB + 8L*1024*512)
#define OFF_XPB   (OFF_XPF  + 8L*64*512)
#define OFF_DTWF  (OFF_XPB  + 8L*64*512)
#define OFF_DTWB  (OFF_DTWF + 8L*512*32)
#define OFF_OWF   (OFF_DTWB + 8L*512*32)
#define OFF_OWB   (OFF_OWF  + 8L*512*512)
#define OFF_WOUT  (OFF_OWB  + 8L*512*512)
#define TOTAL_W   (OFF_WOUT + 8L*256*1024)
__device__ bf16 g_w_hi[TOTAL_W];
__device__ bf16 g_w_lo[TOTAL_W];

__device__ __forceinline__ float siluf(float x) { return x / (1.f + __expf(-x)); }
__device__ __forceinline__ float splusf(float x) { return x > 20.f ? x : log1pf(__expf(x)); }

__device__ __forceinline__ uint32_t smem_u32(const void* p) {
    uint32_t a;
    asm("{ .reg .u64 t; cvta.to.shared.u64 t, %1; cvt.u32.u64 %0, t; }" : "=r"(a) : "l"(p));
    return a;
}

#define LDSM_X4(r, addr) \
    asm volatile("ldmatrix.sync.aligned.m8n8.x4.shared.b16 {%0,%1,%2,%3}, [%4];" \
        : "=r"((r)[0]), "=r"((r)[1]), "=r"((r)[2]), "=r"((r)[3]) : "r"(addr))
#define MMA_BF16(c, a, b0, b1) \
    asm volatile("mma.sync.aligned.m16n8k16.row.col.f32.bf16.bf16.f32 " \
        "{%0,%1,%2,%3}, {%4,%5,%6,%7}, {%8,%9}, {%0,%1,%2,%3};" \
        : "+f"((c)[0]), "+f"((c)[1]), "+f"((c)[2]), "+f"((c)[3]) \
        : "r"((a)[0]), "r"((a)[1]), "r"((a)[2]), "r"((a)[3]), "r"(b0), "r"(b1))
#define CPA16(dst, src, sz) \
    asm volatile("cp.async.cg.shared.global [%0], [%1], 16, %2;" :: "r"(dst), "l"(src), "r"(sz))
#define CP_COMMIT() asm volatile("cp.async.commit_group;" ::: "memory")
#define CP_WAIT0()  asm volatile("cp.async.wait_group 0;" ::: "memory")
#define CP_WAIT1()  asm volatile("cp.async.wait_group 1;" ::: "memory")

__device__ __forceinline__ void bsplit2(float a, float b, uint32_t& hi, uint32_t& lo) {
    bf16 ah = __float2bfloat16_rn(a);
    bf16 bh = __float2bfloat16_rn(b);
    bf16 al = __float2bfloat16_rn(a - __bfloat162float(ah));
    bf16 bl = __float2bfloat16_rn(b - __bfloat162float(bh));
    hi = (uint32_t)__bfloat16_as_ushort(ah) | ((uint32_t)__bfloat16_as_ushort(bh) << 16);
    lo = (uint32_t)__bfloat16_as_ushort(al) | ((uint32_t)__bfloat16_as_ushort(bl) << 16);
}
__device__ __forceinline__ void bsplit1(float a, bf16& h, bf16& l) {
    h = __float2bfloat16_rn(a);
    l = __float2bfloat16_rn(a - __bfloat162float(h));
}

// ------------------------- fused weight preconversion (single launch) ------------------
struct WJobs { const float* p[10]; };

#define N4_0  (8L*1024*256/4)
#define N4_1  (8L*1024*512/4)
#define N4_2  (8L*1024*512/4)
#define N4_3  (8L*64*512/4)
#define N4_4  (8L*64*512/4)
#define N4_5  (8L*512*32/4)
#define N4_6  (8L*512*32/4)
#define N4_7  (8L*512*512/4)
#define N4_8  (8L*512*512/4)
#define N4_9  (8L*256*1024/4)
#define TOTN4 (N4_0+N4_1+N4_2+N4_3+N4_4+N4_5+N4_6+N4_7+N4_8+N4_9)

__global__ void wpre_all_kernel(WJobs jobs)
{
    const long cum[11] = {
        0,
        N4_0,
        N4_0+N4_1,
        N4_0+N4_1+N4_2,
        N4_0+N4_1+N4_2+N4_3,
        N4_0+N4_1+N4_2+N4_3+N4_4,
        N4_0+N4_1+N4_2+N4_3+N4_4+N4_5,
        N4_0+N4_1+N4_2+N4_3+N4_4+N4_5+N4_6,
        N4_0+N4_1+N4_2+N4_3+N4_4+N4_5+N4_6+N4_7,
        N4_0+N4_1+N4_2+N4_3+N4_4+N4_5+N4_6+N4_7+N4_8,
        TOTN4
    };
    const long off4[10] = {
        OFF_WIN/4, OFF_MINF/4, OFF_MINB/4, OFF_XPF/4, OFF_XPB/4,
        OFF_DTWF/4, OFF_DTWB/4, OFF_OWF/4, OFF_OWB/4, OFF_WOUT/4
    };
    long i = (long)blockIdx.x * blockDim.x + threadIdx.x;
    if (i >= TOTN4) return;
    int j = 0;
#pragma unroll
    for (int t = 0; t < 10; t++)
        if (i >= cum[t + 1]) j = t + 1;
    long local = i - cum[j];
    float4 v = reinterpret_cast<const float4*>(jobs.p[j])[local];
    uint2 h, l;
    bsplit2(v.x, v.y, h.x, l.x);
    bsplit2(v.z, v.w, h.y, l.y);
    reinterpret_cast<uint2*>(g_w_hi)[off4[j] + local] = h;
    reinterpret_cast<uint2*>(g_w_lo)[off4[j] + local] = l;
}

// ------------------------- GEMM common -------------------------
#define EPI_NONE     0
#define EPI_SOFTPLUS 1
#define EPI_RESID    2
#define EPI_GATE     3
#define OUT_F32   0
#define OUT_PAIR  1
#define OUT_BOTH  2

// ---- small tile (64x64), 64KB smem, for small-N / small-grid GEMMs ----
#define S64_AHI 0
#define S64_ALO (8*1024)
#define S64_BHI (16*1024)
#define S64_BLO (24*1024)
#define S64_STAGE (32*1024)
#define S64_TOTAL (2*S64_STAGE)

template <int EPI, int OUT>
__global__ __launch_bounds__(256)
void mma_gemm64(const bf16* __restrict__ Ahi0, const bf16* __restrict__ Alo0, int lda, long sA,
                const bf16* __restrict__ WhiF, const bf16* __restrict__ WloF,
                const bf16* __restrict__ WhiB, const bf16* __restrict__ WloB,
                const float* __restrict__ bF, const float* __restrict__ bB,
                float* Cf0, bf16* Chi0, bf16* Clo0, long sC, int ldc,
                const float* __restrict__ resid,
                int M, int N, int K)
{
    extern __shared__ char smem[];
    const int dir = blockIdx.z;
    const bf16* Ahi = Ahi0 + (long)dir * sA;
    const bf16* Alo = Alo0 + (long)dir * sA;
    const bf16* Whi = dir ? WhiB : WhiF;
    const bf16* Wlo = dir ? WloB : WloF;
    const float* bias = dir ? bB : bF;
    float* Cf = Cf0 + (long)dir * sC;
    bf16* Chi = Chi0 + (long)dir * sC;
    bf16* Clo = Clo0 + (long)dir * sC;
    const int czoff = (EPI == EPI_GATE) ? dir * 512 : 0;

    const int tid = threadIdx.x;
    const int wid = tid >> 5;
    const int lane = tid & 31;
    const int bm = blockIdx.y * 64;
    const int bn = blockIdx.x * 64;

    const uint32_t sbase = smem_u32(smem);

    const int mrow = (wid & 3) << 4;
    const int ncol = (wid >> 2) << 5;

    const int lane8 = lane & 7, sel = lane >> 3;
    uint32_t aOff, aXor;
    {
        int row = mrow + (sel & 1) * 8 + lane8;
        int colB = (sel >> 1) * 16;
        aOff = S64_AHI + row * 128 + colB;
        aXor = (uint32_t)((row & 7) << 4);
    }
    uint32_t bOff[2], bXor[2];
#pragma unroll
    for (int nj = 0; nj < 2; nj++) {
        int row = ncol + nj * 16 + (sel >> 1) * 8 + lane8;
        int colB = (sel & 1) * 16;
        bOff[nj] = S64_BHI + row * 128 + colB;
        bXor[nj] = (uint32_t)((row & 7) << 4);
    }

    float acc[4][4];
#pragma unroll
    for (int ni = 0; ni < 4; ni++)
#pragma unroll
        for (int j = 0; j < 4; j++) acc[ni][j] = 0.f;

    const int nch = (K + 63) >> 6;

    auto issue_chunk = [&](int k0, uint32_t stb) {
        const int kw = (K - k0) < 64 ? (K - k0) : 64;
        const int shf = (kw == 64) ? 3 : 2;
        const int msk = (1 << shf) - 1;
        {
            int nseg = 64 << shf;
            for (int idx = tid; idx < nseg; idx += 256) {
                int row = idx >> shf;
                int col8 = (idx & msk) << 3;
                int gm = bm + row;
                uint32_t sz = (gm < M) ? 16u : 0u;
                long srcoff = (long)(gm < M ? gm : 0) * lda + k0 + col8;
                uint32_t off = (uint32_t)(row * 128 + (col8 << 1));
                uint32_t sw = off ^ ((off >> 3) & 0x70);
                CPA16(stb + S64_AHI + sw, Ahi + srcoff, sz);
                CPA16(stb + S64_ALO + sw, Alo + srcoff, sz);
            }
        }
        {
            int nseg = 64 << shf;
            for (int idx = tid; idx < nseg; idx += 256) {
                int row = idx >> shf;
                int col8 = (idx & msk) << 3;
                long srcoff = (long)(bn + row) * K + k0 + col8;
                uint32_t off = (uint32_t)(row * 128 + (col8 << 1));
                uint32_t sw = off ^ ((off >> 3) & 0x70);
                CPA16(stb + S64_BHI + sw, Whi + srcoff, 16u);
                CPA16(stb + S64_BLO + sw, Wlo + srcoff, 16u);
            }
        }
        CP_COMMIT();
    };

    issue_chunk(0, sbase);

    for (int c = 0; c < nch; c++) {
        const uint32_t cur = sbase + (uint32_t)(c & 1) * S64_STAGE;
        if (c + 1 < nch) {
            issue_chunk((c + 1) << 6, sbase + (uint32_t)((c + 1) & 1) * S64_STAGE);
            CP_WAIT1();
        } else {
            CP_WAIT0();
        }
        __syncthreads();

        const int kw = (K - (c << 6)) < 64 ? (K - (c << 6)) : 64;
        const int ksteps = kw >> 4;
#pragma unroll
        for (int s = 0; s < 4; s++) {
            if (s >= ksteps) break;
            uint32_t ah[4], al[4], bh[2][4], bl[2][4];
            {
                uint32_t ad = (cur + aOff + (uint32_t)(s * 32)) ^ aXor;
                LDSM_X4(ah, ad);
                LDSM_X4(al, ad + (S64_ALO - S64_AHI));
            }
#pragma unroll
            for (int nj = 0; nj < 2; nj++) {
                uint32_t bd = (cur + bOff[nj] + (uint32_t)(s * 32)) ^ bXor[nj];
                LDSM_X4(bh[nj], bd);
                LDSM_X4(bl[nj], bd + (S64_BLO - S64_BHI));
            }
#pragma unroll
            for (int nj = 0; nj < 2; nj++) {
#pragma unroll
                for (int blk = 0; blk < 2; blk++) {
                    int ni = nj * 2 + blk;
                    MMA_BF16(acc[ni], ah, bh[nj][blk*2], bh[nj][blk*2+1]);
                    MMA_BF16(acc[ni], ah, bl[nj][blk*2], bl[nj][blk*2+1]);
                    MMA_BF16(acc[ni], al, bh[nj][blk*2], bh[nj][blk*2+1]);
                }
            }
        }
        __syncthreads();
    }

#pragma unroll
    for (int ni = 0; ni < 4; ni++) {
        int n = bn + ncol + ni * 8 + ((lane & 3) << 1);
#pragma unroll
        for (int h = 0; h < 2; h++) {
            int m = bm + mrow + (lane >> 2) + h * 8;
            if (m >= M) continue;
            float2 v = make_float2(acc[ni][h*2], acc[ni][h*2+1]);
            long off = (long)m * ldc + czoff + n;
            if (EPI == EPI_SOFTPLUS) {
                v.x = splusf(v.x + bias[n + 0]);
                v.y = splusf(v.y + bias[n + 1]);
            } else if (EPI == EPI_RESID) {
                float2 r = *reinterpret_cast<const float2*>(resid + off);
                v.x += r.x; v.y += r.y;
            } else if (EPI == EPI_GATE) {
                float2 r = *reinterpret_cast<const float2*>(
                    resid + (long)m * 1024 + 512 + n);
                v.x *= siluf(r.x); v.y *= siluf(r.y);
            }
            if (OUT == OUT_F32 || OUT == OUT_BOTH)
                *reinterpret_cast<float2*>(Cf + off) = v;
            if (OUT == OUT_PAIR || OUT == OUT_BOTH) {
                uint32_t hi, lo;
                bsplit2(v.x, v.y, hi, lo);
                *reinterpret_cast<uint32_t*>(Chi + off) = hi;
                *reinterpret_cast<uint32_t*>(Clo + off) = lo;
            }
        }
    }
}

// ---- big tile (128x128), 128KB smem, 1 blk/SM; halves operand traffic per MAC --------
#define BG_AHI 0
#define BG_ALO (16*1024)
#define BG_BHI (32*1024)
#define BG_BLO (48*1024)
#define BG_STAGE (64*1024)
#define BG_TOTAL (2*BG_STAGE)

template <int EPI, int OUT>
__global__ __launch_bounds__(256)
void mma_gemm_big(const bf16* __restrict__ Ahi0, const bf16* __restrict__ Alo0, int lda, long sA,
                  const bf16* __restrict__ WhiF, const bf16* __restrict__ WloF,
                  const bf16* __restrict__ WhiB, const bf16* __restrict__ WloB,
                  const float* __restrict__ bF, const float* __restrict__ bB,
                  float* Cf0, bf16* Chi0, bf16* Clo0, long sC, int ldc,
                  const float* __restrict__ resid,
                  int M, int N, int K)
{
    extern __shared__ char smem[];
    const int dir = blockIdx.z;
    const bf16* Ahi = Ahi0 + (long)dir * sA;
    const bf16* Alo = Alo0 + (long)dir * sA;
    const bf16* Whi = dir ? WhiB : WhiF;
    const bf16* Wlo = dir ? WloB : WloF;
    const float* bias = dir ? bB : bF;
    float* Cf = Cf0 + (long)dir * sC;
    bf16* Chi = Chi0 + (long)dir * sC;
    bf16* Clo = Clo0 + (long)dir * sC;
    const int czoff = (EPI == EPI_GATE) ? dir * 512 : 0;

    const int tid = threadIdx.x;
    const int wid = tid >> 5;
    const int lane = tid & 31;
    const int bm = blockIdx.y * 128;
    const int bn = blockIdx.x * 128;

    const uint32_t sbase = smem_u32(smem);

    // warp sub-tile: 32(M) x 64(N); 8 warps = 4(M) x 2(N)
    const int mrow = (wid & 3) << 5;
    const int ncol = (wid >> 2) << 6;

    const int lane8 = lane & 7, sel = lane >> 3;
    uint32_t aOff[2], aXor[2];
#pragma unroll
    for (int mi = 0; mi < 2; mi++) {
        int row = mrow + mi * 16 + (sel & 1) * 8 + lane8;
        int colB = (sel >> 1) * 16;
        aOff[mi] = BG_AHI + row * 128 + colB;
        aXor[mi] = (uint32_t)((row & 7) << 4);
    }
    uint32_t bOff[4], bXor[4];
#pragma unroll
    for (int nj = 0; nj < 4; nj++) {
        int row = ncol + nj * 16 + (sel >> 1) * 8 + lane8;
        int colB = (sel & 1) * 16;
        bOff[nj] = BG_BHI + row * 128 + colB;
        bXor[nj] = (uint32_t)((row & 7) << 4);
    }

    float acc[2][8][4];
#pragma unroll
    for (int mi = 0; mi < 2; mi++)
#pragma unroll
        for (int ni = 0; ni < 8; ni++)
#pragma unroll
            for (int j = 0; j < 4; j++) acc[mi][ni][j] = 0.f;

    const int nch = (K + 63) >> 6;

    auto issue_chunk = [&](int k0, uint32_t stb) {
        const int kw = (K - k0) < 64 ? (K - k0) : 64;
        const int shf = (kw == 64) ? 3 : 2;
        const int msk = (1 << shf) - 1;
        {
            int nseg = 128 << shf;
            for (int idx = tid; idx < nseg; idx += 256) {
                int row = idx >> shf;
                int col8 = (idx & msk) << 3;
                int gm = bm + row;
                uint32_t sz = (gm < M) ? 16u : 0u;
                long srcoff = (long)(gm < M ? gm : 0) * lda + k0 + col8;
                uint32_t off = (uint32_t)(row * 128 + (col8 << 1));
                uint32_t sw = off ^ ((off >> 3) & 0x70);
                CPA16(stb + BG_AHI + sw, Ahi + srcoff, sz);
                CPA16(stb + BG_ALO + sw, Alo + srcoff, sz);
            }
        }
        {
            int nseg = 128 << shf;
            for (int idx = tid; idx < nseg; idx += 256) {
                int row = idx >> shf;
                int col8 = (idx & msk) << 3;
                long srcoff = (long)(bn + row) * K + k0 + col8;
                uint32_t off = (uint32_t)(row * 128 + (col8 << 1));
                uint32_t sw = off ^ ((off >> 3) & 0x70);
                CPA16(stb + BG_BHI + sw, Whi + srcoff, 16u);
                CPA16(stb + BG_BLO + sw, Wlo + srcoff, 16u);
            }
        }
        CP_COMMIT();
    };

    issue_chunk(0, sbase);

    for (int c = 0; c < nch; c++) {
        const uint32_t cur = sbase + (uint32_t)(c & 1) * BG_STAGE;
        if (c + 1 < nch) {
            issue_chunk((c + 1) << 6, sbase + (uint32_t)((c + 1) & 1) * BG_STAGE);
            CP_WAIT1();
        } else {
            CP_WAIT0();
        }
        __syncthreads();

        const int kw = (K - (c << 6)) < 64 ? (K - (c << 6)) : 64;
        const int ksteps = kw >> 4;
#pragma unroll
        for (int s = 0; s < 4; s++) {
            if (s >= ksteps) break;
            uint32_t ah[2][4], al[2][4], bh[4][4], bl[4][4];
#pragma unroll
            for (int mi = 0; mi < 2; mi++) {
                uint32_t ad = (cur + aOff[mi] + (uint32_t)(s * 32)) ^ aXor[mi];
                LDSM_X4(ah[mi], ad);
                LDSM_X4(al[mi], ad + (BG_ALO - BG_AHI));
            }
#pragma unroll
            for (int nj = 0; nj < 4; nj++) {
                uint32_t bd = (cur + bOff[nj] + (uint32_t)(s * 32)) ^ bXor[nj];
                LDSM_X4(bh[nj], bd);
                LDSM_X4(bl[nj], bd + (BG_BLO - BG_BHI));
            }
#pragma unroll
            for (int mi = 0; mi < 2; mi++) {
#pragma unroll
                for (int nj = 0; nj < 4; nj++) {
#pragma unroll
                    for (int blk = 0; blk < 2; blk++) {
                        int ni = nj * 2 + blk;
                        MMA_BF16(acc[mi][ni], ah[mi], bh[nj][blk*2], bh[nj][blk*2+1]);
                        MMA_BF16(acc[mi][ni], ah[mi], bl[nj][blk*2], bl[nj][blk*2+1]);
                        MMA_BF16(acc[mi][ni], al[mi], bh[nj][blk*2], bh[nj][blk*2+1]);
                    }
                }
            }
        }
        __syncthreads();
    }

#pragma unroll
    for (int mi = 0; mi < 2; mi++) {
#pragma unroll
        for (int ni = 0; ni < 8; ni++) {
            int n = bn + ncol + ni * 8 + ((lane & 3) << 1);
#pragma unroll
            for (int h = 0; h < 2; h++) {
                int m = bm + mrow + mi * 16 + (lane >> 2) + h * 8;
                if (m >= M) continue;
                float2 v = make_float2(acc[mi][ni][h*2], acc[mi][ni][h*2+1]);
                long off = (long)m * ldc + czoff + n;
                if (EPI == EPI_SOFTPLUS) {
                    v.x = splusf(v.x + bias[n + 0]);
                    v.y = splusf(v.y + bias[n + 1]);
                } else if (EPI == EPI_RESID) {
                    float2 r = *reinterpret_cast<const float2*>(resid + off);
                    v.x += r.x; v.y += r.y;
                } else if (EPI == EPI_GATE) {
                    float2 r = *reinterpret_cast<const float2*>(
                        resid + (long)m * 1024 + 512 + n);
                    v.x *= siluf(r.x); v.y *= siluf(r.y);
                }
                if (OUT == OUT_F32 || OUT == OUT_BOTH)
                    *reinterpret_cast<float2*>(Cf + off) = v;
                if (OUT == OUT_PAIR || OUT == OUT_BOTH) {
                    uint32_t hi, lo;
                    bsplit2(v.x, v.y, hi, lo);
                    *reinterpret_cast<uint32_t*>(Chi + off) = hi;
                    *reinterpret_cast<uint32_t*>(Clo + off) = lo;
                }
            }
        }
    }
}

// ------------------------- patch embedding (FFMA gemm, K=1290) + cls -------------------
__global__ void patch_kernel(const float* __restrict__ x, const float* __restrict__ pw,
                             const float* __restrict__ pb, const float* __restrict__ cls)
{
    const int K = 1290;
    __shared__ float As[16][68];
    __shared__ float Ws[16][68];
    int tid = threadIdx.x;

    if (blockIdx.x == 0 && blockIdx.y == 0) {
#pragma unroll
        for (int i = tid; i < 4 * DM; i += 256) {
            int b = i >> 8, c = i & 255;
            g_h[((long)b * SEQ) * DM + c] = cls[c];
        }
    }

    int tx = tid & 15, ty = tid >> 4;
    int bm = blockIdx.y * 64, bn = blockIdx.x * 64;
    int arow = tid >> 2;
    int akq = (tid & 3) << 2;

    int mload = bm + arow;
    bool mvalid = mload < 2000;
    int bb = mvalid ? (mload / NPOS) : 0;
    int ppos = mvalid ? (mload - bb * NPOS) : 0;
    const float* xbase = x + (long)bb * 129 * 5000 + ppos * 10;
    const float* wbase = pw + (long)(bn + arow) * K;

    float acc[4][4];
#pragma unroll
    for (int i = 0; i < 4; i++)
#pragma unroll
        for (int j = 0; j < 4; j++) acc[i][j] = 0.f;

    for (int k0 = 0; k0 < K; k0 += 16) {
#pragma unroll
        for (int j = 0; j < 4; j++) {
            int kk = k0 + akq + j;
            float a = 0.f, w = 0.f;
            if (kk < K) {
                if (mvalid) {
                    int i10 = kk / 10;
                    int r = kk - i10 * 10;
                    a = xbase[(long)i10 * 5000 + r];
                }
                w = wbase[kk];
            }
            As[akq + j][arow] = a;
            Ws[akq + j][arow] = w;
        }
        __syncthreads();
#pragma unroll
        for (int kk = 0; kk < 16; kk++) {
            float4 a4 = *reinterpret_cast<const float4*>(&As[kk][ty << 2]);
            float4 w4 = *reinterpret_cast<const float4*>(&Ws[kk][tx << 2]);
            acc[0][0] = fmaf(a4.x, w4.x, acc[0][0]); acc[0][1] = fmaf(a4.x, w4.y, acc[0][1]);
            acc[0][2] = fmaf(a4.x, w4.z, acc[0][2]); acc[0][3] = fmaf(a4.x, w4.w, acc[0][3]);
            acc[1][0] = fmaf(a4.y, w4.x, acc[1][0]); acc[1][1] = fmaf(a4.y, w4.y, acc[1][1]);
            acc[1][2] = fmaf(a4.y, w4.z, acc[1][2]); acc[1][3] = fmaf(a4.y, w4.w, acc[1][3]);
            acc[2][0] = fmaf(a4.z, w4.x, acc[2][0]); acc[2][1] = fmaf(a4.z, w4.y, acc[2][1]);
            acc[2][2] = fmaf(a4.z, w4.z, acc[2][2]); acc[2][3] = fmaf(a4.z, w4.w, acc[2][3]);
            acc[3][0] = fmaf(a4.w, w4.x, acc[3][0]); acc[3][1] = fmaf(a4.w, w4.y, acc[3][1]);
            acc[3][2] = fmaf(a4.w, w4.z, acc[3][2]); acc[3][3] = fmaf(a4.w, w4.w, acc[3][3]);
        }
        __syncthreads();
    }
#pragma unroll
    for (int i = 0; i < 4; i++) {
        int m = bm + (ty << 2) + i;
        if (m >= 2000) continue;
        int b = m / NPOS, p = m - (m / NPOS) * NPOS;
        long orow = ((long)b * SEQ + 1 + p) * DM;
#pragma unroll
        for (int j = 0; j < 4; j++) {
            int n = bn + (tx << 2) + j;
            g_h[orow + n] = acc[i][j] + pb[n];
        }
    }
}

// ------------------------- causal depthwise conv (K=4) + SiLU, x4 vectorized -----------
__global__ void conv_silu_kernel(const float* __restrict__ X0, long sX, int xpitch,
                                 const float* __restrict__ wF, const float* __restrict__ wB,
                                 const float* __restrict__ bF, const float* __restrict__ bB,
                                 float* Yf0, bf16* Yhi0, bf16* Ylo0, long sY, int rev_dir1)
{
    int dir = blockIdx.z;
    const float* X = X0 + (long)dir * sX;
    const float* w = dir ? wB : wF;
    const float* bias = dir ? bB : bF;
    int rev = dir & rev_dir1;

    const int NV = BL * (DI / 4);
    int idx = blockIdx.x * blockDim.x + threadIdx.x;
    if (idx >= NV) return;
    int d4 = idx & 127;
    int m = idx >> 7;
    int b = m / SEQ, l = m - b * SEQ;
    int d = d4 << 2;

    float4 acc = *reinterpret_cast<const float4*>(bias + d);
    float4 w0 = *reinterpret_cast<const float4*>(w + (d + 0) * 4);
    float4 w1 = *reinterpret_cast<const float4*>(w + (d + 1) * 4);
    float4 w2 = *reinterpret_cast<const float4*>(w + (d + 2) * 4);
    float4 w3 = *reinterpret_cast<const float4*>(w + (d + 3) * 4);
    const float* wp0 = reinterpret_cast<const float*>(&w0);
    const float* wp1 = reinterpret_cast<const float*>(&w1);
    const float* wp2 = reinterpret_cast<const float*>(&w2);
    const float* wp3 = reinterpret_cast<const float*>(&w3);

#pragma unroll
    for (int k = 0; k < 4; k++) {
        int ll = rev ? (l + 3 - k) : (l + k - 3);
        if (ll >= 0 && ll < SEQ) {
            float4 xv = *reinterpret_cast<const float4*>(
                X + ((long)(b * SEQ + ll)) * xpitch + d);
            acc.x = fmaf(xv.x, wp0[k], acc.x);
            acc.y = fmaf(xv.y, wp1[k], acc.y);
            acc.z = fmaf(xv.z, wp2[k], acc.z);
            acc.w = fmaf(xv.w, wp3[k], acc.w);
        }
    }
    float4 y = make_float4(siluf(acc.x), siluf(acc.y), siluf(acc.z), siluf(acc.w));
    long o = (long)dir * sY + (long)m * DI + d;
    if (Yf0) *reinterpret_cast<float4*>(Yf0 + o) = y;
    uint2 h, l2;
    bsplit2(y.x, y.y, h.x, l2.x);
    bsplit2(y.z, y.w, h.y, l2.y);
    *reinterpret_cast<uint2*>(Yhi0 + o) = h;
    *reinterpret_cast<uint2*>(Ylo0 + o) = l2;
}

// ------------------------- selective scan v2: grouped prefetch, short h-chain ----------
__global__ void scan_kernel(const float* __restrict__ Alf, const float* __restrict__ Alb,
                            const float* __restrict__ Df,  const float* __restrict__ Db)
{
    int tid = threadIdx.x;
    int g = blockIdx.x * 16 + (tid >> 4);
    int n = tid & 15;
    int dir = g >> 11;
    int b = (g >> 9) & 3;
    int d = g & 511;

    const float* Al = dir ? Alb : Alf;
    const float* Dp = dir ? Db : Df;
    float Ac = -__expf(Al[d * 16 + n]);
    float Dv = Dp[d];

    const float* u_     = g_u     + (long)dir * BL * DI;
    const float* delta_ = g_delta + (long)dir * BL * DI;
    const float* dbc_   = g_dbc   + (long)dir * BL * 64;
    const float* zb_    = g_xz    + (long)dir * BL * 1024 + DI;
    bf16* yhi_          = g_yg_hi + (long)dir * BL * DI;
    bf16* ylo_          = g_yg_lo + (long)dir * BL * DI;

    const int step = dir ? -1 : 1;
    long m0 = (long)b * SEQ + (dir ? SEQ - 1 : 0);

    const float* pd = delta_ + m0 * DI + d;
    const float* pu = u_     + m0 * DI + d;
    const float* pB = dbc_   + m0 * 64 + 32 + n;
    const float* pC = dbc_   + m0 * 64 + 48 + n;
    const float* pz = zb_    + m0 * 1024 + d;
    bf16* ph = yhi_ + m0 * DI + d;
    bf16* pl = ylo_ + m0 * DI + d;

    const long sD  = (long)step * DI;
    const long sB4 = (long)step * 64;
    const long sZ  = (long)step * 1024;

    float h = 0.f;
    float dv[4], uv[4], Bv[4], Cv[4], zv[4];

#pragma unroll
    for (int j = 0; j < 4; j++) {
        dv[j] = pd[j * sD];
        uv[j] = pu[j * sD];
        Bv[j] = pB[j * sB4];
        Cv[j] = pC[j * sB4];
        zv[j] = (n == 0) ? pz[j * sZ] : 0.f;
    }

    const int NG = 125;
    for (int grp = 0; grp < NG; grp++) {
        float dA[4], dBu[4], uD[4], Cc[4], zg[4];
#pragma unroll
        for (int j = 0; j < 4; j++) {
            dA[j]  = __expf(dv[j] * Ac);
            dBu[j] = dv[j] * Bv[j] * uv[j];
            uD[j]  = uv[j] * Dv;
            Cc[j]  = Cv[j];
            zg[j]  = zv[j];
        }
        if (grp + 1 < NG) {
#pragma unroll
            for (int j = 0; j < 4; j++) {
                dv[j] = pd[(4 + j) * sD];
                uv[j] = pu[(4 + j) * sD];
                Bv[j] = pB[(4 + j) * sB4];
                Cv[j] = pC[(4 + j) * sB4];
                zv[j] = (n == 0) ? pz[(4 + j) * sZ] : 0.f;
            }
        } else {
            dv[0] = pd[4 * sD];
            uv[0] = pu[4 * sD];
            Bv[0] = pB[4 * sB4];
            Cv[0] = pC[4 * sB4];
            zv[0] = (n == 0) ? pz[4 * sZ] : 0.f;
        }
#pragma unroll
        for (int j = 0; j < 4; j++) {
            h = fmaf(dA[j], h, dBu[j]);
            float p = h * Cc[j];
            p += __shfl_xor_sync(0xffffffffu, p, 8);
            p += __shfl_xor_sync(0xffffffffu, p, 4);
            p += __shfl_xor_sync(0xffffffffu, p, 2);
            p += __shfl_xor_sync(0xffffffffu, p, 1);
            if (n == 0) {
                float y = (p + uD[j]) * siluf(zg[j]);
                bf16 hh, ll;
                bsplit1(y, hh, ll);
                ph[j * sD] = hh;
                pl[j * sD] = ll;
            }
        }
        pd += 4 * sD; pu += 4 * sD; pB += 4 * sB4; pC += 4 * sB4; pz += 4 * sZ;
        ph += 4 * sD; pl += 4 * sD;
    }
    {
        float dA = __expf(dv[0] * Ac);
        h = fmaf(dA, h, dv[0] * Bv[0] * uv[0]);
        float p = h * Cv[0];
        p += __shfl_xor_sync(0xffffffffu, p, 8);
        p += __shfl_xor_sync(0xffffffffu, p, 4);
        p += __shfl_xor_sync(0xffffffffu, p, 2);
        p += __shfl_xor_sync(0xffffffffu, p, 1);
        if (n == 0) {
            float y = (p + uv[0] * Dv) * siluf(zv[0]);
            bf16 hh, ll;
            bsplit1(y, hh, ll);
            ph[0] = hh;
            pl[0] = ll;
        }
    }
}

// ------------------------- layernorm (256 wide) -------------------------
__global__ void ln_kernel(const float* __restrict__ X, const float* __restrict__ gg,
                          const float* __restrict__ bb,
                          float* __restrict__ Yf, bf16* __restrict__ Yhi,
                          bf16* __restrict__ Ylo, int rowStride)
{
    int row = blockIdx.x * rowStride;
    int tid = threadIdx.x;
    float v = X[(long)row * DM + tid];
    float s = v, sq = v * v;
#pragma unroll
    for (int o = 16; o > 0; o >>= 1) {
        s  += __shfl_xor_sync(0xffffffffu, s, o);
        sq += __shfl_xor_sync(0xffffffffu, sq, o);
    }
    __shared__ float ss[8], sq2[8];
    int wid = tid >> 5, lane = tid & 31;
    if (lane == 0) { ss[wid] = s; sq2[wid] = sq; }
    __syncthreads();
    float ts = 0.f, tq = 0.f;
#pragma unroll
    for (int i = 0; i < 8; i++) { ts += ss[i]; tq += sq2[i]; }
    float mean = ts * (1.f / DM);
    float var = tq * (1.f / DM) - mean * mean;
    float inv = rsqrtf(var + 1e-5f);
    float y = (v - mean) * inv * gg[tid] + bb[tid];
    long o = (long)blockIdx.x * DM + tid;
    if (Yf) Yf[o] = y;
    if (Yhi) {
        bf16 hh, ll2;
        bsplit1(y, hh, ll2);
        Yhi[o] = hh;
        Ylo[o] = ll2;
    }
}

// ------------------------- host orchestration -------------------------
extern "C" void kernel_launch(void* const* d_in, const int* in_sizes, int n_in,
                              void* d_out, int out_size)
{
    const bool sig_order = (in_sizes[9] == 8 * 1024 * 512);

    const float* x       = (const float*)d_in[0];
    const float* patch_w = (const float*)d_in[1];
    const float* patch_b = (const float*)d_in[2];
    const float* cls     = (const float*)d_in[3];
    const float* ln_g    = (const float*)d_in[4];
    const float* ln_b    = (const float*)d_in[5];
    const float* in_w    = (const float*)d_in[6];
    const float* cw      = (const float*)d_in[7];
    const float* cb      = (const float*)d_in[8];

    const float *out_w, *fn_g, *fn_b;
    const float *mf_in, *mf_cw, *mf_cb, *mf_xp, *mf_dtw, *mf_dtb, *mf_Al, *mf_D, *mf_ow;
    const float *mb_in, *mb_cw, *mb_cb, *mb_xp, *mb_dtw, *mb_dtb, *mb_Al, *mb_D, *mb_ow;

    if (sig_order) {
        mf_in  = (const float*)d_in[9];  mf_cw  = (const float*)d_in[10];
        mf_cb  = (const float*)d_in[11]; mf_xp  = (const float*)d_in[12];
        mf_dtw = (const float*)d_in[13]; mf_dtb = (const float*)d_in[14];
        mf_Al  = (const float*)d_in[15]; mf_D   = (const float*)d_in[16];
        mf_ow  = (const float*)d_in[17];
        mb_in  = (const float*)d_in[18]; mb_cw  = (const float*)d_in[19];
        mb_cb  = (const float*)d_in[20]; mb_xp  = (const float*)d_in[21];
        mb_dtw = (const float*)d_in[22]; mb_dtb = (const float*)d_in[23];
        mb_Al  = (const float*)d_in[24]; mb_D   = (const float*)d_in[25];
        mb_ow  = (const float*)d_in[26];
        out_w  = (const float*)d_in[27];
        fn_g   = (const float*)d_in[28]; fn_b   = (const float*)d_in[29];
    } else {
        out_w  = (const float*)d_in[9];
        fn_g   = (const float*)d_in[10]; fn_b   = (const float*)d_in[11];
        mf_in  = (const float*)d_in[12]; mf_cw  = (const float*)d_in[13];
        mf_cb  = (const float*)d_in[14]; mf_xp  = (const float*)d_in[15];
        mf_dtw = (const float*)d_in[16]; mf_dtb = (const float*)d_in[17];
        mf_Al  = (const float*)d_in[18]; mf_D   = (const float*)d_in[19];
        mf_ow  = (const float*)d_in[20];
        mb_in  = (const float*)d_in[21]; mb_cw  = (const float*)d_in[22];
        mb_cb  = (const float*)d_in[23]; mb_xp  = (const float*)d_in[24];
        mb_dtw = (const float*)d_in[25]; mb_dtb = (const float*)d_in[26];
        mb_Al  = (const float*)d_in[27]; mb_D   = (const float*)d_in[28];
        mb_ow  = (const float*)d_in[29];
    }

    float *p_h, *p_xcres, *p_xz, *p_u, *p_dbc, *p_delta;
    bf16 *p_xn_hi, *p_xn_lo, *p_xc_hi, *p_xc_lo, *p_u_hi, *p_u_lo;
    bf16 *p_dbc_hi, *p_dbc_lo, *p_yg_hi, *p_yg_lo, *p_cat_hi, *p_cat_lo;
    bf16 *p_whi, *p_wlo;
    cudaGetSymbolAddress((void**)&p_h, g_h);
    cudaGetSymbolAddress((void**)&p_xcres, g_xcres);
    cudaGetSymbolAddress((void**)&p_xz, g_xz);
    cudaGetSymbolAddress((void**)&p_u, g_u);
    cudaGetSymbolAddress((void**)&p_dbc, g_dbc);
    cudaGetSymbolAddress((void**)&p_delta, g_delta);
    cudaGetSymbolAddress((void**)&p_xn_hi, g_xn_hi);
    cudaGetSymbolAddress((void**)&p_xn_lo, g_xn_lo);
    cudaGetSymbolAddress((void**)&p_xc_hi, g_xc_hi);
    cudaGetSymbolAddress((void**)&p_xc_lo, g_xc_lo);
    cudaGetSymbolAddress((void**)&p_u_hi, g_u_hi);
    cudaGetSymbolAddress((void**)&p_u_lo, g_u_lo);
    cudaGetSymbolAddress((void**)&p_dbc_hi, g_dbc_hi);
    cudaGetSymbolAddress((void**)&p_dbc_lo, g_dbc_lo);
    cudaGetSymbolAddress((void**)&p_yg_hi, g_yg_hi);
    cudaGetSymbolAddress((void**)&p_yg_lo, g_yg_lo);
    cudaGetSymbolAddress((void**)&p_cat_hi, g_cat_hi);
    cudaGetSymbolAddress((void**)&p_cat_lo, g_cat_lo);
    cudaGetSymbolAddress((void**)&p_whi, g_w_hi);
    cudaGetSymbolAddress((void**)&p_wlo, g_w_lo);

    cudaFuncSetAttribute(mma_gemm64<EPI_NONE,OUT_BOTH>,    cudaFuncAttributeMaxDynamicSharedMemorySize, S64_TOTAL);
    cudaFuncSetAttribute(mma_gemm64<EPI_SOFTPLUS,OUT_F32>, cudaFuncAttributeMaxDynamicSharedMemorySize, S64_TOTAL);
    cudaFuncSetAttribute(mma_gemm64<EPI_RESID,OUT_F32>,    cudaFuncAttributeMaxDynamicSharedMemorySize, S64_TOTAL);
    cudaFuncSetAttribute(mma_gemm_big<EPI_NONE,OUT_F32>,   cudaFuncAttributeMaxDynamicSharedMemorySize, BG_TOTAL);
    cudaFuncSetAttribute(mma_gemm_big<EPI_GATE,OUT_PAIR>,  cudaFuncAttributeMaxDynamicSharedMemorySize, BG_TOTAL);

    const int MT64  = (BL + 63) / 64;    // 32 row tiles
    const int MT128 = (BL + 127) / 128;  // 16 row tiles
    const long sXZ = (long)BL * 1024;
    const long sDI = (long)BL * DI;
    const long sDBC = (long)BL * 64;
    const int CONV_G = (BL * (DI / 4) + 255) / 256;

    // ---- fused weight preconversion (1 launch) ----
    {
        WJobs jobs;
        jobs.p[0] = in_w;   jobs.p[1] = mf_in;  jobs.p[2] = mb_in;
        jobs.p[3] = mf_xp;  jobs.p[4] = mb_xp;  jobs.p[5] = mf_dtw;
        jobs.p[6] = mb_dtw; jobs.p[7] = mf_ow;  jobs.p[8] = mb_ow;
        jobs.p[9] = out_w;
        long grid = (TOTN4 + 255) / 256;
        wpre_all_kernel<<<(int)grid, 256>>>(jobs);
    }

    // patch embed (+cls fused)
    patch_kernel<<<dim3(DM / 64, (2000 + 63) / 64), 256>>>(x, patch_w, patch_b, cls);

    for (int l = 0; l < NLAYER; l++) {
        // 1) layernorm -> xn hi/lo
        ln_kernel<<<BL, DM>>>(p_h, ln_g + l * 256, ln_b + l * 256,
                              nullptr, p_xn_hi, p_xn_lo, 1);
        // 2) block in-proj (128x128 tile): xn @ in_w^T -> xcres fp32
        {
            bf16* whi = p_whi + OFF_WIN + (long)l * 1024 * 256;
            bf16* wlo = p_wlo + OFF_WIN + (long)l * 1024 * 256;
            mma_gemm_big<EPI_NONE,OUT_F32><<<dim3(8, MT128, 1), 256, BG_TOTAL>>>(
                p_xn_hi, p_xn_lo, 256, 0, whi, wlo, whi, wlo, nullptr, nullptr,
                p_xcres, nullptr, nullptr, 0, 1024, nullptr, BL, 1024, 256);
        }
        // 3) block conv+silu: xcres[:, :512] -> xc hi/lo
        conv_silu_kernel<<<dim3(CONV_G, 1, 1), 256>>>(
            p_xcres, 0, 1024, cw + l * 2048, cw + l * 2048, cb + l * 512, cb + l * 512,
            nullptr, p_xc_hi, p_xc_lo, 0, 0);
        // 4) mamba in-proj (128x128 tile, both dirs): xc @ {mf,mb}_in^T -> xz fp32
        mma_gemm_big<EPI_NONE,OUT_F32><<<dim3(8, MT128, 2), 256, BG_TOTAL>>>(
            p_xc_hi, p_xc_lo, 512, 0,
            p_whi + OFF_MINF + (long)l * 1024 * 512, p_wlo + OFF_MINF + (long)l * 1024 * 512,
            p_whi + OFF_MINB + (long)l * 1024 * 512, p_wlo + OFF_MINB + (long)l * 1024 * 512,
            nullptr, nullptr, p_xz, nullptr, nullptr, sXZ, 1024, nullptr, BL, 1024, 512);
        // 5) mamba conv+silu (dir-aware): xz[dir][:, :512] -> u fp32 + hi/lo
        conv_silu_kernel<<<dim3(CONV_G, 1, 2), 256>>>(
            p_xz, sXZ, 1024, mf_cw + l * 2048, mb_cw + l * 2048,
            mf_cb + l * 512, mb_cb + l * 512, p_u, p_u_hi, p_u_lo, sDI, 1);
        // 6) x-proj (64 tile): u @ xp^T -> dbc fp32 + hi/lo
        mma_gemm64<EPI_NONE,OUT_BOTH><<<dim3(1, MT64, 2), 256, S64_TOTAL>>>(
            p_u_hi, p_u_lo, 512, sDI,
            p_whi + OFF_XPF + (long)l * 64 * 512, p_wlo + OFF_XPF + (long)l * 64 * 512,
            p_whi + OFF_XPB + (long)l * 64 * 512, p_wlo + OFF_XPB + (long)l * 64 * 512,
            nullptr, nullptr, p_dbc, p_dbc_hi, p_dbc_lo, sDBC, 64, nullptr, BL, 64, 512);
        // 7) delta = softplus(dt @ dtw^T + dtb) fp32 (64 tile)
        mma_gemm64<EPI_SOFTPLUS,OUT_F32><<<dim3(8, MT64, 2), 256, S64_TOTAL>>>(
            p_dbc_hi, p_dbc_lo, 64, sDBC,
            p_whi + OFF_DTWF + (long)l * 512 * 32, p_wlo + OFF_DTWF + (long)l * 512 * 32,
            p_whi + OFF_DTWB + (long)l * 512 * 32, p_wlo + OFF_DTWB + (long)l * 512 * 32,
            mf_dtb + l * 512, mb_dtb + l * 512,
            p_delta, nullptr, nullptr, sDI, 512, nullptr, BL, 512, 32);
        // 8) selective scan -> yg hi/lo
        scan_kernel<<<256, 256>>>(mf_Al + l * 8192, mb_Al + l * 8192,
                                  mf_D + l * 512, mb_D + l * 512);
        // 9) out-proj + gate + concat (128x128 tile): cat[:, dir*512:] = (yg@ow^T)*silu(res)
        mma_gemm_big<EPI_GATE,OUT_PAIR><<<dim3(4, MT128, 2), 256, BG_TOTAL>>>(
            p_yg_hi, p_yg_lo, 512, sDI,
            p_whi + OFF_OWF + (long)l * 512 * 512, p_wlo + OFF_OWF + (long)l * 512 * 512,
            p_whi + OFF_OWB + (long)l * 512 * 512, p_wlo + OFF_OWB + (long)l * 512 * 512,
            nullptr, nullptr, nullptr, p_cat_hi, p_cat_lo, 0, 1024, p_xcres, BL, 512, 512);
        // 10) block out-proj + residual (64 tile): h = cat @ out_w^T + h
        {
            bf16* whi = p_whi + OFF_WOUT + (long)l * 256 * 1024;
            bf16* wlo = p_wlo + OFF_WOUT + (long)l * 256 * 1024;
            mma_gemm64<EPI_RESID,OUT_F32><<<dim3(4, MT64, 1), 256, S64_TOTAL>>>(
                p_cat_hi, p_cat_lo, 1024, 0, whi, wlo, whi, wlo, nullptr, nullptr,
                p_h, nullptr, nullptr, 0, 256, p_h, BL, DM, 1024);
        }
    }

    // final layernorm on cls rows -> output (4 x 256)
    ln_kernel<<<BATCH, DM>>>(p_h, fn_g, fn_b, (float*)d_out, nullptr, nullptr, SEQ);
}

// round 17
// speedup vs baseline: 1.0843x; 1.0843x over previous
#include <cuda_runtime.h>
#include <cuda_fp16.h>
#include <math.h>
#include <stdint.h>

typedef __half f16;

#define BATCH   4
#define SEQ     501
#define BL      (BATCH*SEQ)     // 2004
#define NPOS    500
#define DM      256
#define DI      512
#define NLAYER  8

// ------------------------- scratch (device globals; no allocs) -------------------------
__device__ float g_h[BL*DM];
__device__ float g_xcres[BL*1024];
__device__ float g_xz[2L*BL*1024];
__device__ float g_u[2L*BL*DI];
__device__ float g_dbc[2L*BL*64];
__device__ float g_delta[2L*BL*DI];

__device__ f16 g_xn_hi[BL*DM],    g_xn_lo[BL*DM];
__device__ f16 g_xc_hi[BL*DI],    g_xc_lo[BL*DI];
__device__ f16 g_u_hi[2L*BL*DI],  g_u_lo[2L*BL*DI];
__device__ f16 g_dbc_hi[2L*BL*64],g_dbc_lo[2L*BL*64];
__device__ f16 g_yg_hi[2L*BL*DI], g_yg_lo[2L*BL*DI];
__device__ f16 g_cat_hi[BL*1024], g_cat_lo[BL*1024];

// preconverted-weight arena (fp16 hi only — split-2 scheme)
#define OFF_WIN   0L
#define OFF_MINF  (OFF_WIN  + 8L*1024*256)
#define OFF_MINB  (OFF_MINF + 8L*1024*512)
#define OFF_XPF   (OFF_MINB + 8L*1024*512)
#define OFF_XPB   (OFF_XPF  + 8L*64*512)
#define OFF_DTWF  (OFF_XPB  + 8L*64*512)
#define OFF_DTWB  (OFF_DTWF + 8L*512*32)
#define OFF_OWF   (OFF_DTWB + 8L*512*32)
#define OFF_OWB   (OFF_OWF  + 8L*512*512)
#define OFF_WOUT  (OFF_OWB  + 8L*512*512)
#define TOTAL_W   (OFF_WOUT + 8L*256*1024)
__device__ f16 g_w_hi[TOTAL_W];

__device__ __forceinline__ float siluf(float x) { return x / (1.f + __expf(-x)); }
__device__ __forceinline__ float splusf(float x) { return x > 20.f ? x : log1pf(__expf(x)); }

__device__ __forceinline__ uint32_t smem_u32(const void* p) {
    uint32_t a;
    asm("{ .reg .u64 t; cvta.to.shared.u64 t, %1; cvt.u32.u64 %0, t; }" : "=r"(a) : "l"(p));
    return a;
}

#define LDSM_X4(r, addr) \
    asm volatile("ldmatrix.sync.aligned.m8n8.x4.shared.b16 {%0,%1,%2,%3}, [%4];" \
        : "=r"((r)[0]), "=r"((r)[1]), "=r"((r)[2]), "=r"((r)[3]) : "r"(addr))
#define MMA_F16(c, a, b0, b1) \
    asm volatile("mma.sync.aligned.m16n8k16.row.col.f32.f16.f16.f32 " \
        "{%0,%1,%2,%3}, {%4,%5,%6,%7}, {%8,%9}, {%0,%1,%2,%3};" \
        : "+f"((c)[0]), "+f"((c)[1]), "+f"((c)[2]), "+f"((c)[3]) \
        : "r"((a)[0]), "r"((a)[1]), "r"((a)[2]), "r"((a)[3]), "r"(b0), "r"(b1))
#define CPA16(dst, src, sz) \
    asm volatile("cp.async.cg.shared.global [%0], [%1], 16, %2;" :: "r"(dst), "l"(src), "r"(sz))
#define CP_COMMIT() asm volatile("cp.async.commit_group;" ::: "memory")
#define CP_WAIT0()  asm volatile("cp.async.wait_group 0;" ::: "memory")
#define CP_WAIT1()  asm volatile("cp.async.wait_group 1;" ::: "memory")

__device__ __forceinline__ void fsplit2(float a, float b, uint32_t& hi, uint32_t& lo) {
    f16 ah = __float2half_rn(a);
    f16 bh = __float2half_rn(b);
    f16 al = __float2half_rn(a - __half2float(ah));
    f16 bl = __float2half_rn(b - __half2float(bh));
    hi = (uint32_t)__half_as_ushort(ah) | ((uint32_t)__half_as_ushort(bh) << 16);
    lo = (uint32_t)__half_as_ushort(al) | ((uint32_t)__half_as_ushort(bl) << 16);
}
__device__ __forceinline__ void fsplit1(float a, f16& h, f16& l) {
    h = __float2half_rn(a);
    l = __float2half_rn(a - __half2float(h));
}
__device__ __forceinline__ void fhi2(float a, float b, uint32_t& hi) {
    f16 ah = __float2half_rn(a);
    f16 bh = __float2half_rn(b);
    hi = (uint32_t)__half_as_ushort(ah) | ((uint32_t)__half_as_ushort(bh) << 16);
}

// ------------------------- fused weight preconversion (single launch) ------------------
struct WJobs { const float* p[10]; };

#define N4_0  (8L*1024*256/4)
#define N4_1  (8L*1024*512/4)
#define N4_2  (8L*1024*512/4)
#define N4_3  (8L*64*512/4)
#define N4_4  (8L*64*512/4)
#define N4_5  (8L*512*32/4)
#define N4_6  (8L*512*32/4)
#define N4_7  (8L*512*512/4)
#define N4_8  (8L*512*512/4)
#define N4_9  (8L*256*1024/4)
#define TOTN4 (N4_0+N4_1+N4_2+N4_3+N4_4+N4_5+N4_6+N4_7+N4_8+N4_9)

__global__ void wpre_all_kernel(WJobs jobs)
{
    const long cum[11] = {
        0,
        N4_0,
        N4_0+N4_1,
        N4_0+N4_1+N4_2,
        N4_0+N4_1+N4_2+N4_3,
        N4_0+N4_1+N4_2+N4_3+N4_4,
        N4_0+N4_1+N4_2+N4_3+N4_4+N4_5,
        N4_0+N4_1+N4_2+N4_3+N4_4+N4_5+N4_6,
        N4_0+N4_1+N4_2+N4_3+N4_4+N4_5+N4_6+N4_7,
        N4_0+N4_1+N4_2+N4_3+N4_4+N4_5+N4_6+N4_7+N4_8,
        TOTN4
    };
    const long off4[10] = {
        OFF_WIN/4, OFF_MINF/4, OFF_MINB/4, OFF_XPF/4, OFF_XPB/4,
        OFF_DTWF/4, OFF_DTWB/4, OFF_OWF/4, OFF_OWB/4, OFF_WOUT/4
    };
    long i = (long)blockIdx.x * blockDim.x + threadIdx.x;
    if (i >= TOTN4) return;
    int j = 0;
#pragma unroll
    for (int t = 0; t < 10; t++)
        if (i >= cum[t + 1]) j = t + 1;
    long local = i - cum[j];
    float4 v = reinterpret_cast<const float4*>(jobs.p[j])[local];
    uint2 h;
    fhi2(v.x, v.y, h.x);
    fhi2(v.z, v.w, h.y);
    reinterpret_cast<uint2*>(g_w_hi)[off4[j] + local] = h;
}

// ------------------------- GEMM common -------------------------
#define EPI_NONE     0
#define EPI_SOFTPLUS 1
#define EPI_RESID    2
#define EPI_GATE     3
#define OUT_F32   0
#define OUT_PAIR  1
#define OUT_BOTH  2

// ---- small tile (64x64): A hi/lo + B hi; stage 24KB, total 48KB ----
#define S64_AHI 0
#define S64_ALO (8*1024)
#define S64_BHI (16*1024)
#define S64_STAGE (24*1024)
#define S64_TOTAL (2*S64_STAGE)

template <int EPI, int OUT>
__global__ __launch_bounds__(256)
void mma_gemm64(const f16* __restrict__ Ahi0, const f16* __restrict__ Alo0, int lda, long sA,
                const f16* __restrict__ WhiF, const f16* __restrict__ WhiB,
                const float* __restrict__ bF, const float* __restrict__ bB,
                float* Cf0, f16* Chi0, f16* Clo0, long sC, int ldc,
                const float* __restrict__ resid,
                int M, int N, int K)
{
    extern __shared__ char smem[];
    const int dir = blockIdx.z;
    const f16* Ahi = Ahi0 + (long)dir * sA;
    const f16* Alo = Alo0 + (long)dir * sA;
    const f16* Whi = dir ? WhiB : WhiF;
    const float* bias = dir ? bB : bF;
    float* Cf = Cf0 + (long)dir * sC;
    f16* Chi = Chi0 + (long)dir * sC;
    f16* Clo = Clo0 + (long)dir * sC;
    const int czoff = (EPI == EPI_GATE) ? dir * 512 : 0;

    const int tid = threadIdx.x;
    const int wid = tid >> 5;
    const int lane = tid & 31;
    const int bm = blockIdx.y * 64;
    const int bn = blockIdx.x * 64;

    const uint32_t sbase = smem_u32(smem);

    const int mrow = (wid & 3) << 4;
    const int ncol = (wid >> 2) << 5;

    const int lane8 = lane & 7, sel = lane >> 3;
    uint32_t aOff, aXor;
    {
        int row = mrow + (sel & 1) * 8 + lane8;
        int colB = (sel >> 1) * 16;
        aOff = S64_AHI + row * 128 + colB;
        aXor = (uint32_t)((row & 7) << 4);
    }
    uint32_t bOff[2], bXor[2];
#pragma unroll
    for (int nj = 0; nj < 2; nj++) {
        int row = ncol + nj * 16 + (sel >> 1) * 8 + lane8;
        int colB = (sel & 1) * 16;
        bOff[nj] = S64_BHI + row * 128 + colB;
        bXor[nj] = (uint32_t)((row & 7) << 4);
    }

    float acc[4][4];
#pragma unroll
    for (int ni = 0; ni < 4; ni++)
#pragma unroll
        for (int j = 0; j < 4; j++) acc[ni][j] = 0.f;

    const int nch = (K + 63) >> 6;

    auto issue_chunk = [&](int k0, uint32_t stb) {
        const int kw = (K - k0) < 64 ? (K - k0) : 64;
        const int shf = (kw == 64) ? 3 : 2;
        const int msk = (1 << shf) - 1;
        {
            int nseg = 64 << shf;
            for (int idx = tid; idx < nseg; idx += 256) {
                int row = idx >> shf;
                int col8 = (idx & msk) << 3;
                int gm = bm + row;
                uint32_t sz = (gm < M) ? 16u : 0u;
                long srcoff = (long)(gm < M ? gm : 0) * lda + k0 + col8;
                uint32_t off = (uint32_t)(row * 128 + (col8 << 1));
                uint32_t sw = off ^ ((off >> 3) & 0x70);
                CPA16(stb + S64_AHI + sw, Ahi + srcoff, sz);
                CPA16(stb + S64_ALO + sw, Alo + srcoff, sz);
            }
        }
        {
            int nseg = 64 << shf;
            for (int idx = tid; idx < nseg; idx += 256) {
                int row = idx >> shf;
                int col8 = (idx & msk) << 3;
                long srcoff = (long)(bn + row) * K + k0 + col8;
                uint32_t off = (uint32_t)(row * 128 + (col8 << 1));
                uint32_t sw = off ^ ((off >> 3) & 0x70);
                CPA16(stb + S64_BHI + sw, Whi + srcoff, 16u);
            }
        }
        CP_COMMIT();
    };

    issue_chunk(0, sbase);

    for (int c = 0; c < nch; c++) {
        const uint32_t cur = sbase + (uint32_t)(c & 1) * S64_STAGE;
        if (c + 1 < nch) {
            issue_chunk((c + 1) << 6, sbase + (uint32_t)((c + 1) & 1) * S64_STAGE);
            CP_WAIT1();
        } else {
            CP_WAIT0();
        }
        __syncthreads();

        const int kw = (K - (c << 6)) < 64 ? (K - (c << 6)) : 64;
        const int ksteps = kw >> 4;
#pragma unroll
        for (int s = 0; s < 4; s++) {
            if (s >= ksteps) break;
            uint32_t ah[4], al[4], bh[2][4];
            {
                uint32_t ad = (cur + aOff + (uint32_t)(s * 32)) ^ aXor;
                LDSM_X4(ah, ad);
                LDSM_X4(al, ad + (S64_ALO - S64_AHI));
            }
#pragma unroll
            for (int nj = 0; nj < 2; nj++) {
                uint32_t bd = (cur + bOff[nj] + (uint32_t)(s * 32)) ^ bXor[nj];
                LDSM_X4(bh[nj], bd);
            }
#pragma unroll
            for (int nj = 0; nj < 2; nj++) {
#pragma unroll
                for (int blk = 0; blk < 2; blk++) {
                    int ni = nj * 2 + blk;
                    MMA_F16(acc[ni], ah, bh[nj][blk*2], bh[nj][blk*2+1]);
                    MMA_F16(acc[ni], al, bh[nj][blk*2], bh[nj][blk*2+1]);
                }
            }
        }
        __syncthreads();
    }

#pragma unroll
    for (int ni = 0; ni < 4; ni++) {
        int n = bn + ncol + ni * 8 + ((lane & 3) << 1);
#pragma unroll
        for (int h = 0; h < 2; h++) {
            int m = bm + mrow + (lane >> 2) + h * 8;
            if (m >= M) continue;
            float2 v = make_float2(acc[ni][h*2], acc[ni][h*2+1]);
            long off = (long)m * ldc + czoff + n;
            if (EPI == EPI_SOFTPLUS) {
                v.x = splusf(v.x + bias[n + 0]);
                v.y = splusf(v.y + bias[n + 1]);
            } else if (EPI == EPI_RESID) {
                float2 r = *reinterpret_cast<const float2*>(resid + off);
                v.x += r.x; v.y += r.y;
            } else if (EPI == EPI_GATE) {
                float2 r = *reinterpret_cast<const float2*>(
                    resid + (long)m * 1024 + 512 + n);
                v.x *= siluf(r.x); v.y *= siluf(r.y);
            }
            if (OUT == OUT_F32 || OUT == OUT_BOTH)
                *reinterpret_cast<float2*>(Cf + off) = v;
            if (OUT == OUT_PAIR || OUT == OUT_BOTH) {
                uint32_t hi, lo;
                fsplit2(v.x, v.y, hi, lo);
                *reinterpret_cast<uint32_t*>(Chi + off) = hi;
                *reinterpret_cast<uint32_t*>(Clo + off) = lo;
            }
        }
    }
}

// ---- big tile (128x64): A hi/lo 32KB + B hi 8KB; stage 40KB, total 80KB ----
#define SB_AHI 0
#define SB_ALO (16*1024)
#define SB_BHI (32*1024)
#define SB_STAGE (40*1024)
#define SB_TOTAL (2*SB_STAGE)

template <int EPI, int OUT>
__global__ __launch_bounds__(256)
void mma_gemm128(const f16* __restrict__ Ahi0, const f16* __restrict__ Alo0, int lda, long sA,
                 const f16* __restrict__ WhiF, const f16* __restrict__ WhiB,
                 const float* __restrict__ bF, const float* __restrict__ bB,
                 float* Cf0, f16* Chi0, f16* Clo0, long sC, int ldc,
                 const float* __restrict__ resid,
                 int M, int N, int K)
{
    extern __shared__ char smem[];
    const int dir = blockIdx.z;
    const f16* Ahi = Ahi0 + (long)dir * sA;
    const f16* Alo = Alo0 + (long)dir * sA;
    const f16* Whi = dir ? WhiB : WhiF;
    const float* bias = dir ? bB : bF;
    float* Cf = Cf0 + (long)dir * sC;
    f16* Chi = Chi0 + (long)dir * sC;
    f16* Clo = Clo0 + (long)dir * sC;
    const int czoff = (EPI == EPI_GATE) ? dir * 512 : 0;

    const int tid = threadIdx.x;
    const int wid = tid >> 5;
    const int lane = tid & 31;
    const int bm = blockIdx.y * 128;
    const int bn = blockIdx.x * 64;

    const uint32_t sbase = smem_u32(smem);

    const int mrow = (wid & 3) << 5;
    const int ncol = (wid >> 2) << 5;

    const int lane8 = lane & 7, sel = lane >> 3;
    uint32_t aOff[2], aXor[2];
#pragma unroll
    for (int mi = 0; mi < 2; mi++) {
        int row = mrow + mi * 16 + (sel & 1) * 8 + lane8;
        int colB = (sel >> 1) * 16;
        aOff[mi] = SB_AHI + row * 128 + colB;
        aXor[mi] = (uint32_t)((row & 7) << 4);
    }
    uint32_t bOff[2], bXor[2];
#pragma unroll
    for (int nj = 0; nj < 2; nj++) {
        int row = ncol + nj * 16 + (sel >> 1) * 8 + lane8;
        int colB = (sel & 1) * 16;
        bOff[nj] = SB_BHI + row * 128 + colB;
        bXor[nj] = (uint32_t)((row & 7) << 4);
    }

    float acc[2][4][4];
#pragma unroll
    for (int mi = 0; mi < 2; mi++)
#pragma unroll
        for (int ni = 0; ni < 4; ni++)
#pragma unroll
            for (int j = 0; j < 4; j++) acc[mi][ni][j] = 0.f;

    const int nch = (K + 63) >> 6;

    auto issue_chunk = [&](int k0, uint32_t stb) {
        const int kw = (K - k0) < 64 ? (K - k0) : 64;
        const int shf = (kw == 64) ? 3 : 2;
        const int msk = (1 << shf) - 1;
        {
            int nseg = 128 << shf;
            for (int idx = tid; idx < nseg; idx += 256) {
                int row = idx >> shf;
                int col8 = (idx & msk) << 3;
                int gm = bm + row;
                uint32_t sz = (gm < M) ? 16u : 0u;
                long srcoff = (long)(gm < M ? gm : 0) * lda + k0 + col8;
                uint32_t off = (uint32_t)(row * 128 + (col8 << 1));
                uint32_t sw = off ^ ((off >> 3) & 0x70);
                CPA16(stb + SB_AHI + sw, Ahi + srcoff, sz);
                CPA16(stb + SB_ALO + sw, Alo + srcoff, sz);
            }
        }
        {
            int nseg = 64 << shf;
            for (int idx = tid; idx < nseg; idx += 256) {
                int row = idx >> shf;
                int col8 = (idx & msk) << 3;
                long srcoff = (long)(bn + row) * K + k0 + col8;
                uint32_t off = (uint32_t)(row * 128 + (col8 << 1));
                uint32_t sw = off ^ ((off >> 3) & 0x70);
                CPA16(stb + SB_BHI + sw, Whi + srcoff, 16u);
            }
        }
        CP_COMMIT();
    };

    issue_chunk(0, sbase);

    for (int c = 0; c < nch; c++) {
        const uint32_t cur = sbase + (uint32_t)(c & 1) * SB_STAGE;
        if (c + 1 < nch) {
            issue_chunk((c + 1) << 6, sbase + (uint32_t)((c + 1) & 1) * SB_STAGE);
            CP_WAIT1();
        } else {
            CP_WAIT0();
        }
        __syncthreads();

        const int kw = (K - (c << 6)) < 64 ? (K - (c << 6)) : 64;
        const int ksteps = kw >> 4;
#pragma unroll
        for (int s = 0; s < 4; s++) {
            if (s >= ksteps) break;
            uint32_t ah[2][4], al[2][4], bh[2][4];
#pragma unroll
            for (int mi = 0; mi < 2; mi++) {
                uint32_t ad = (cur + aOff[mi] + (uint32_t)(s * 32)) ^ aXor[mi];
                LDSM_X4(ah[mi], ad);
                LDSM_X4(al[mi], ad + (SB_ALO - SB_AHI));
            }
#pragma unroll
            for (int nj = 0; nj < 2; nj++) {
                uint32_t bd = (cur + bOff[nj] + (uint32_t)(s * 32)) ^ bXor[nj];
                LDSM_X4(bh[nj], bd);
            }
#pragma unroll
            for (int mi = 0; mi < 2; mi++) {
#pragma unroll
                for (int nj = 0; nj < 2; nj++) {
#pragma unroll
                    for (int blk = 0; blk < 2; blk++) {
                        int ni = nj * 2 + blk;
                        MMA_F16(acc[mi][ni], ah[mi], bh[nj][blk*2], bh[nj][blk*2+1]);
                        MMA_F16(acc[mi][ni], al[mi], bh[nj][blk*2], bh[nj][blk*2+1]);
                    }
                }
            }
        }
        __syncthreads();
    }

#pragma unroll
    for (int mi = 0; mi < 2; mi++) {
#pragma unroll
        for (int ni = 0; ni < 4; ni++) {
            int n = bn + ncol + ni * 8 + ((lane & 3) << 1);
#pragma unroll
            for (int h = 0; h < 2; h++) {
                int m = bm + mrow + mi * 16 + (lane >> 2) + h * 8;
                if (m >= M) continue;
                float2 v = make_float2(acc[mi][ni][h*2], acc[mi][ni][h*2+1]);
                long off = (long)m * ldc + czoff + n;
                if (EPI == EPI_SOFTPLUS) {
                    v.x = splusf(v.x + bias[n + 0]);
                    v.y = splusf(v.y + bias[n + 1]);
                } else if (EPI == EPI_RESID) {
                    float2 r = *reinterpret_cast<const float2*>(resid + off);
                    v.x += r.x; v.y += r.y;
                } else if (EPI == EPI_GATE) {
                    float2 r = *reinterpret_cast<const float2*>(
                        resid + (long)m * 1024 + 512 + n);
                    v.x *= siluf(r.x); v.y *= siluf(r.y);
                }
                if (OUT == OUT_F32 || OUT == OUT_BOTH)
                    *reinterpret_cast<float2*>(Cf + off) = v;
                if (OUT == OUT_PAIR || OUT == OUT_BOTH) {
                    uint32_t hi, lo;
                    fsplit2(v.x, v.y, hi, lo);
                    *reinterpret_cast<uint32_t*>(Chi + off) = hi;
                    *reinterpret_cast<uint32_t*>(Clo + off) = lo;
                }
            }
        }
    }
}

// ------------------------- patch embedding (FFMA gemm, K=1290) + cls -------------------
__global__ void patch_kernel(const float* __restrict__ x, const float* __restrict__ pw,
                             const float* __restrict__ pb, const float* __restrict__ cls)
{
    const int K = 1290;
    __shared__ float As[16][68];
    __shared__ float Ws[16][68];
    int tid = threadIdx.x;

    if (blockIdx.x == 0 && blockIdx.y == 0) {
#pragma unroll
        for (int i = tid; i < 4 * DM; i += 256) {
            int b = i >> 8, c = i & 255;
            g_h[((long)b * SEQ) * DM + c] = cls[c];
        }
    }

    int tx = tid & 15, ty = tid >> 4;
    int bm = blockIdx.y * 64, bn = blockIdx.x * 64;
    int arow = tid >> 2;
    int akq = (tid & 3) << 2;

    int mload = bm + arow;
    bool mvalid = mload < 2000;
    int bb = mvalid ? (mload / NPOS) : 0;
    int ppos = mvalid ? (mload - bb * NPOS) : 0;
    const float* xbase = x + (long)bb * 129 * 5000 + ppos * 10;
    const float* wbase = pw + (long)(bn + arow) * K;

    float acc[4][4];
#pragma unroll
    for (int i = 0; i < 4; i++)
#pragma unroll
        for (int j = 0; j < 4; j++) acc[i][j] = 0.f;

    for (int k0 = 0; k0 < K; k0 += 16) {
#pragma unroll
        for (int j = 0; j < 4; j++) {
            int kk = k0 + akq + j;
            float a = 0.f, w = 0.f;
            if (kk < K) {
                if (mvalid) {
                    int i10 = kk / 10;
                    int r = kk - i10 * 10;
                    a = xbase[(long)i10 * 5000 + r];
                }
                w = wbase[kk];
            }
            As[akq + j][arow] = a;
            Ws[akq + j][arow] = w;
        }
        __syncthreads();
#pragma unroll
        for (int kk = 0; kk < 16; kk++) {
            float4 a4 = *reinterpret_cast<const float4*>(&As[kk][ty << 2]);
            float4 w4 = *reinterpret_cast<const float4*>(&Ws[kk][tx << 2]);
            acc[0][0] = fmaf(a4.x, w4.x, acc[0][0]); acc[0][1] = fmaf(a4.x, w4.y, acc[0][1]);
            acc[0][2] = fmaf(a4.x, w4.z, acc[0][2]); acc[0][3] = fmaf(a4.x, w4.w, acc[0][3]);
            acc[1][0] = fmaf(a4.y, w4.x, acc[1][0]); acc[1][1] = fmaf(a4.y, w4.y, acc[1][1]);
            acc[1][2] = fmaf(a4.y, w4.z, acc[1][2]); acc[1][3] = fmaf(a4.y, w4.w, acc[1][3]);
            acc[2][0] = fmaf(a4.z, w4.x, acc[2][0]); acc[2][1] = fmaf(a4.z, w4.y, acc[2][1]);
            acc[2][2] = fmaf(a4.z, w4.z, acc[2][2]); acc[2][3] = fmaf(a4.z, w4.w, acc[2][3]);
            acc[3][0] = fmaf(a4.w, w4.x, acc[3][0]); acc[3][1] = fmaf(a4.w, w4.y, acc[3][1]);
            acc[3][2] = fmaf(a4.w, w4.z, acc[3][2]); acc[3][3] = fmaf(a4.w, w4.w, acc[3][3]);
        }
        __syncthreads();
    }
#pragma unroll
    for (int i = 0; i < 4; i++) {
        int m = bm + (ty << 2) + i;
        if (m >= 2000) continue;
        int b = m / NPOS, p = m - (m / NPOS) * NPOS;
        long orow = ((long)b * SEQ + 1 + p) * DM;
#pragma unroll
        for (int j = 0; j < 4; j++) {
            int n = bn + (tx << 2) + j;
            g_h[orow + n] = acc[i][j] + pb[n];
        }
    }
}

// ------------------------- causal depthwise conv (K=4) + SiLU, x4 vectorized -----------
__global__ void conv_silu_kernel(const float* __restrict__ X0, long sX, int xpitch,
                                 const float* __restrict__ wF, const float* __restrict__ wB,
                                 const float* __restrict__ bF, const float* __restrict__ bB,
                                 float* Yf0, f16* Yhi0, f16* Ylo0, long sY, int rev_dir1)
{
    int dir = blockIdx.z;
    const float* X = X0 + (long)dir * sX;
    const float* w = dir ? wB : wF;
    const float* bias = dir ? bB : bF;
    int rev = dir & rev_dir1;

    const int NV = BL * (DI / 4);
    int idx = blockIdx.x * blockDim.x + threadIdx.x;
    if (idx >= NV) return;
    int d4 = idx & 127;
    int m = idx >> 7;
    int b = m / SEQ, l = m - b * SEQ;
    int d = d4 << 2;

    float4 acc = *reinterpret_cast<const float4*>(bias + d);
    float4 w0 = *reinterpret_cast<const float4*>(w + (d + 0) * 4);
    float4 w1 = *reinterpret_cast<const float4*>(w + (d + 1) * 4);
    float4 w2 = *reinterpret_cast<const float4*>(w + (d + 2) * 4);
    float4 w3 = *reinterpret_cast<const float4*>(w + (d + 3) * 4);
    const float* wp0 = reinterpret_cast<const float*>(&w0);
    const float* wp1 = reinterpret_cast<const float*>(&w1);
    const float* wp2 = reinterpret_cast<const float*>(&w2);
    const float* wp3 = reinterpret_cast<const float*>(&w3);

#pragma unroll
    for (int k = 0; k < 4; k++) {
        int ll = rev ? (l + 3 - k) : (l + k - 3);
        if (ll >= 0 && ll < SEQ) {
            float4 xv = *reinterpret_cast<const float4*>(
                X + ((long)(b * SEQ + ll)) * xpitch + d);
            acc.x = fmaf(xv.x, wp0[k], acc.x);
            acc.y = fmaf(xv.y, wp1[k], acc.y);
            acc.z = fmaf(xv.z, wp2[k], acc.z);
            acc.w = fmaf(xv.w, wp3[k], acc.w);
        }
    }
    float4 y = make_float4(siluf(acc.x), siluf(acc.y), siluf(acc.z), siluf(acc.w));
    long o = (long)dir * sY + (long)m * DI + d;
    if (Yf0) *reinterpret_cast<float4*>(Yf0 + o) = y;
    uint2 h, l2;
    fsplit2(y.x, y.y, h.x, l2.x);
    fsplit2(y.z, y.w, h.y, l2.y);
    *reinterpret_cast<uint2*>(Yhi0 + o) = h;
    *reinterpret_cast<uint2*>(Ylo0 + o) = l2;
}

// ------------------------- selective scan v2: grouped prefetch, short h-chain ----------
__global__ void scan_kernel(const float* __restrict__ Alf, const float* __restrict__ Alb,
                            const float* __restrict__ Df,  const float* __restrict__ Db)
{
    int tid = threadIdx.x;
    int g = blockIdx.x * 16 + (tid >> 4);
    int n = tid & 15;
    int dir = g >> 11;
    int b = (g >> 9) & 3;
    int d = g & 511;

    const float* Al = dir ? Alb : Alf;
    const float* Dp = dir ? Db : Df;
    float Ac = -__expf(Al[d * 16 + n]);
    float Dv = Dp[d];

    const float* u_     = g_u     + (long)dir * BL * DI;
    const float* delta_ = g_delta + (long)dir * BL * DI;
    const float* dbc_   = g_dbc   + (long)dir * BL * 64;
    const float* zb_    = g_xz    + (long)dir * BL * 1024 + DI;
    f16* yhi_           = g_yg_hi + (long)dir * BL * DI;
    f16* ylo_           = g_yg_lo + (long)dir * BL * DI;

    const int step = dir ? -1 : 1;
    long m0 = (long)b * SEQ + (dir ? SEQ - 1 : 0);

    const float* pd = delta_ + m0 * DI + d;
    const float* pu = u_     + m0 * DI + d;
    const float* pB = dbc_   + m0 * 64 + 32 + n;
    const float* pC = dbc_   + m0 * 64 + 48 + n;
    const float* pz = zb_    + m0 * 1024 + d;
    f16* ph = yhi_ + m0 * DI + d;
    f16* pl = ylo_ + m0 * DI + d;

    const long sD  = (long)step * DI;
    const long sB4 = (long)step * 64;
    const long sZ  = (long)step * 1024;

    float h = 0.f;
    float dv[4], uv[4], Bv[4], Cv[4], zv[4];

#pragma unroll
    for (int j = 0; j < 4; j++) {
        dv[j] = pd[j * sD];
        uv[j] = pu[j * sD];
        Bv[j] = pB[j * sB4];
        Cv[j] = pC[j * sB4];
        zv[j] = (n == 0) ? pz[j * sZ] : 0.f;
    }

    const int NG = 125;
    for (int grp = 0; grp < NG; grp++) {
        float dA[4], dBu[4], uD[4], Cc[4], zg[4];
#pragma unroll
        for (int j = 0; j < 4; j++) {
            dA[j]  = __expf(dv[j] * Ac);
            dBu[j] = dv[j] * Bv[j] * uv[j];
            uD[j]  = uv[j] * Dv;
            Cc[j]  = Cv[j];
            zg[j]  = zv[j];
        }
        if (grp + 1 < NG) {
#pragma unroll
            for (int j = 0; j < 4; j++) {
                dv[j] = pd[(4 + j) * sD];
                uv[j] = pu[(4 + j) * sD];
                Bv[j] = pB[(4 + j) * sB4];
                Cv[j] = pC[(4 + j) * sB4];
                zv[j] = (n == 0) ? pz[(4 + j) * sZ] : 0.f;
            }
        } else {
            dv[0] = pd[4 * sD];
            uv[0] = pu[4 * sD];
            Bv[0] = pB[4 * sB4];
            Cv[0] = pC[4 * sB4];
            zv[0] = (n == 0) ? pz[4 * sZ] : 0.f;
        }
#pragma unroll
        for (int j = 0; j < 4; j++) {
            h = fmaf(dA[j], h, dBu[j]);
            float p = h * Cc[j];
            p += __shfl_xor_sync(0xffffffffu, p, 8);
            p += __shfl_xor_sync(0xffffffffu, p, 4);
            p += __shfl_xor_sync(0xffffffffu, p, 2);
            p += __shfl_xor_sync(0xffffffffu, p, 1);
            if (n == 0) {
                float y = (p + uD[j]) * siluf(zg[j]);
                f16 hh, ll;
                fsplit1(y, hh, ll);
                ph[j * sD] = hh;
                pl[j * sD] = ll;
            }
        }
        pd += 4 * sD; pu += 4 * sD; pB += 4 * sB4; pC += 4 * sB4; pz += 4 * sZ;
        ph += 4 * sD; pl += 4 * sD;
    }
    {
        float dA = __expf(dv[0] * Ac);
        h = fmaf(dA, h, dv[0] * Bv[0] * uv[0]);
        float p = h * Cv[0];
        p += __shfl_xor_sync(0xffffffffu, p, 8);
        p += __shfl_xor_sync(0xffffffffu, p, 4);
        p += __shfl_xor_sync(0xffffffffu, p, 2);
        p += __shfl_xor_sync(0xffffffffu, p, 1);
        if (n == 0) {
            float y = (p + uv[0] * Dv) * siluf(zv[0]);
            f16 hh, ll;
            fsplit1(y, hh, ll);
            ph[0] = hh;
            pl[0] = ll;
        }
    }
}

// ------------------------- layernorm (256 wide) -------------------------
__global__ void ln_kernel(const float* __restrict__ X, const float* __restrict__ gg,
                          const float* __restrict__ bb,
                          float* __restrict__ Yf, f16* __restrict__ Yhi,
                          f16* __restrict__ Ylo, int rowStride)
{
    int row = blockIdx.x * rowStride;
    int tid = threadIdx.x;
    float v = X[(long)row * DM + tid];
    float s = v, sq = v * v;
#pragma unroll
    for (int o = 16; o > 0; o >>= 1) {
        s  += __shfl_xor_sync(0xffffffffu, s, o);
        sq += __shfl_xor_sync(0xffffffffu, sq, o);
    }
    __shared__ float ss[8], sq2[8];
    int wid = tid >> 5, lane = tid & 31;
    if (lane == 0) { ss[wid] = s; sq2[wid] = sq; }
    __syncthreads();
    float ts = 0.f, tq = 0.f;
#pragma unroll
    for (int i = 0; i < 8; i++) { ts += ss[i]; tq += sq2[i]; }
    float mean = ts * (1.f / DM);
    float var = tq * (1.f / DM) - mean * mean;
    float inv = rsqrtf(var + 1e-5f);
    float y = (v - mean) * inv * gg[tid] + bb[tid];
    long o = (long)blockIdx.x * DM + tid;
    if (Yf) Yf[o] = y;
    if (Yhi) {
        f16 hh, ll2;
        fsplit1(y, hh, ll2);
        Yhi[o] = hh;
        Ylo[o] = ll2;
    }
}

// ------------------------- host orchestration -------------------------
extern "C" void kernel_launch(void* const* d_in, const int* in_sizes, int n_in,
                              void* d_out, int out_size)
{
    const bool sig_order = (in_sizes[9] == 8 * 1024 * 512);

    const float* x       = (const float*)d_in[0];
    const float* patch_w = (const float*)d_in[1];
    const float* patch_b = (const float*)d_in[2];
    const float* cls     = (const float*)d_in[3];
    const float* ln_g    = (const float*)d_in[4];
    const float* ln_b    = (const float*)d_in[5];
    const float* in_w    = (const float*)d_in[6];
    const float* cw      = (const float*)d_in[7];
    const float* cb      = (const float*)d_in[8];

    const float *out_w, *fn_g, *fn_b;
    const float *mf_in, *mf_cw, *mf_cb, *mf_xp, *mf_dtw, *mf_dtb, *mf_Al, *mf_D, *mf_ow;
    const float *mb_in, *mb_cw, *mb_cb, *mb_xp, *mb_dtw, *mb_dtb, *mb_Al, *mb_D, *mb_ow;

    if (sig_order) {
        mf_in  = (const float*)d_in[9];  mf_cw  = (const float*)d_in[10];
        mf_cb  = (const float*)d_in[11]; mf_xp  = (const float*)d_in[12];
        mf_dtw = (const float*)d_in[13]; mf_dtb = (const float*)d_in[14];
        mf_Al  = (const float*)d_in[15]; mf_D   = (const float*)d_in[16];
        mf_ow  = (const float*)d_in[17];
        mb_in  = (const float*)d_in[18]; mb_cw  = (const float*)d_in[19];
        mb_cb  = (const float*)d_in[20]; mb_xp  = (const float*)d_in[21];
        mb_dtw = (const float*)d_in[22]; mb_dtb = (const float*)d_in[23];
        mb_Al  = (const float*)d_in[24]; mb_D   = (const float*)d_in[25];
        mb_ow  = (const float*)d_in[26];
        out_w  = (const float*)d_in[27];
        fn_g   = (const float*)d_in[28]; fn_b   = (const float*)d_in[29];
    } else {
        out_w  = (const float*)d_in[9];
        fn_g   = (const float*)d_in[10]; fn_b   = (const float*)d_in[11];
        mf_in  = (const float*)d_in[12]; mf_cw  = (const float*)d_in[13];
        mf_cb  = (const float*)d_in[14]; mf_xp  = (const float*)d_in[15];
        mf_dtw = (const float*)d_in[16]; mf_dtb = (const float*)d_in[17];
        mf_Al  = (const float*)d_in[18]; mf_D   = (const float*)d_in[19];
        mf_ow  = (const float*)d_in[20];
        mb_in  = (const float*)d_in[21]; mb_cw  = (const float*)d_in[22];
        mb_cb  = (const float*)d_in[23]; mb_xp  = (const float*)d_in[24];
        mb_dtw = (const float*)d_in[25]; mb_dtb = (const float*)d_in[26];
        mb_Al  = (const float*)d_in[27]; mb_D   = (const float*)d_in[28];
        mb_ow  = (const float*)d_in[29];
    }

    float *p_h, *p_xcres, *p_xz, *p_u, *p_dbc, *p_delta;
    f16 *p_xn_hi, *p_xn_lo, *p_xc_hi, *p_xc_lo, *p_u_hi, *p_u_lo;
    f16 *p_dbc_hi, *p_dbc_lo, *p_yg_hi, *p_yg_lo, *p_cat_hi, *p_cat_lo;
    f16 *p_whi;
    cudaGetSymbolAddress((void**)&p_h, g_h);
    cudaGetSymbolAddress((void**)&p_xcres, g_xcres);
    cudaGetSymbolAddress((void**)&p_xz, g_xz);
    cudaGetSymbolAddress((void**)&p_u, g_u);
    cudaGetSymbolAddress((void**)&p_dbc, g_dbc);
    cudaGetSymbolAddress((void**)&p_delta, g_delta);
    cudaGetSymbolAddress((void**)&p_xn_hi, g_xn_hi);
    cudaGetSymbolAddress((void**)&p_xn_lo, g_xn_lo);
    cudaGetSymbolAddress((void**)&p_xc_hi, g_xc_hi);
    cudaGetSymbolAddress((void**)&p_xc_lo, g_xc_lo);
    cudaGetSymbolAddress((void**)&p_u_hi, g_u_hi);
    cudaGetSymbolAddress((void**)&p_u_lo, g_u_lo);
    cudaGetSymbolAddress((void**)&p_dbc_hi, g_dbc_hi);
    cudaGetSymbolAddress((void**)&p_dbc_lo, g_dbc_lo);
    cudaGetSymbolAddress((void**)&p_yg_hi, g_yg_hi);
    cudaGetSymbolAddress((void**)&p_yg_lo, g_yg_lo);
    cudaGetSymbolAddress((void**)&p_cat_hi, g_cat_hi);
    cudaGetSymbolAddress((void**)&p_cat_lo, g_cat_lo);
    cudaGetSymbolAddress((void**)&p_whi, g_w_hi);

    cudaFuncSetAttribute(mma_gemm64<EPI_NONE,OUT_BOTH>,    cudaFuncAttributeMaxDynamicSharedMemorySize, S64_TOTAL);
    cudaFuncSetAttribute(mma_gemm64<EPI_SOFTPLUS,OUT_F32>, cudaFuncAttributeMaxDynamicSharedMemorySize, S64_TOTAL);
    cudaFuncSetAttribute(mma_gemm64<EPI_RESID,OUT_F32>,    cudaFuncAttributeMaxDynamicSharedMemorySize, S64_TOTAL);
    cudaFuncSetAttribute(mma_gemm128<EPI_NONE,OUT_F32>,    cudaFuncAttributeMaxDynamicSharedMemorySize, SB_TOTAL);
    cudaFuncSetAttribute(mma_gemm128<EPI_GATE,OUT_PAIR>,   cudaFuncAttributeMaxDynamicSharedMemorySize, SB_TOTAL);

    const int MT64  = (BL + 63) / 64;    // 32 row tiles
    const int MT128 = (BL + 127) / 128;  // 16 row tiles
    const long sXZ = (long)BL * 1024;
    const long sDI = (long)BL * DI;
    const long sDBC = (long)BL * 64;
    const int CONV_G = (BL * (DI / 4) + 255) / 256;

    // ---- fused weight preconversion (1 launch, fp16 hi only) ----
    {
        WJobs jobs;
        jobs.p[0] = in_w;   jobs.p[1] = mf_in;  jobs.p[2] = mb_in;
        jobs.p[3] = mf_xp;  jobs.p[4] = mb_xp;  jobs.p[5] = mf_dtw;
        jobs.p[6] = mb_dtw; jobs.p[7] = mf_ow;  jobs.p[8] = mb_ow;
        jobs.p[9] = out_w;
        long grid = (TOTN4 + 255) / 256;
        wpre_all_kernel<<<(int)grid, 256>>>(jobs);
    }

    // patch embed (+cls fused)
    patch_kernel<<<dim3(DM / 64, (2000 + 63) / 64), 256>>>(x, patch_w, patch_b, cls);

    for (int l = 0; l < NLAYER; l++) {
        // 1) layernorm -> xn hi/lo
        ln_kernel<<<BL, DM>>>(p_h, ln_g + l * 256, ln_b + l * 256,
                              nullptr, p_xn_hi, p_xn_lo, 1);
        // 2) block in-proj (128x64 tile): xn @ in_w^T -> xcres fp32
        {
            f16* whi = p_whi + OFF_WIN + (long)l * 1024 * 256;
            mma_gemm128<EPI_NONE,OUT_F32><<<dim3(16, MT128, 1), 256, SB_TOTAL>>>(
                p_xn_hi, p_xn_lo, 256, 0, whi, whi, nullptr, nullptr,
                p_xcres, nullptr, nullptr, 0, 1024, nullptr, BL, 1024, 256);
        }
        // 3) block conv+silu: xcres[:, :512] -> xc hi/lo
        conv_silu_kernel<<<dim3(CONV_G, 1, 1), 256>>>(
            p_xcres, 0, 1024, cw + l * 2048, cw + l * 2048, cb + l * 512, cb + l * 512,
            nullptr, p_xc_hi, p_xc_lo, 0, 0);
        // 4) mamba in-proj (128x64 tile, both dirs): xc @ {mf,mb}_in^T -> xz fp32
        mma_gemm128<EPI_NONE,OUT_F32><<<dim3(16, MT128, 2), 256, SB_TOTAL>>>(
            p_xc_hi, p_xc_lo, 512, 0,
            p_whi + OFF_MINF + (long)l * 1024 * 512,
            p_whi + OFF_MINB + (long)l * 1024 * 512,
            nullptr, nullptr, p_xz, nullptr, nullptr, sXZ, 1024, nullptr, BL, 1024, 512);
        // 5) mamba conv+silu (dir-aware): xz[dir][:, :512] -> u fp32 + hi/lo
        conv_silu_kernel<<<dim3(CONV_G, 1, 2), 256>>>(
            p_xz, sXZ, 1024, mf_cw + l * 2048, mb_cw + l * 2048,
            mf_cb + l * 512, mb_cb + l * 512, p_u, p_u_hi, p_u_lo, sDI, 1);
        // 6) x-proj (64 tile): u @ xp^T -> dbc fp32 + hi/lo
        mma_gemm64<EPI_NONE,OUT_BOTH><<<dim3(1, MT64, 2), 256, S64_TOTAL>>>(
            p_u_hi, p_u_lo, 512, sDI,
            p_whi + OFF_XPF + (long)l * 64 * 512,
            p_whi + OFF_XPB + (long)l * 64 * 512,
            nullptr, nullptr, p_dbc, p_dbc_hi, p_dbc_lo, sDBC, 64, nullptr, BL, 64, 512);
        // 7) delta = softplus(dt @ dtw^T + dtb) fp32 (64 tile)
        mma_gemm64<EPI_SOFTPLUS,OUT_F32><<<dim3(8, MT64, 2), 256, S64_TOTAL>>>(
            p_dbc_hi, p_dbc_lo, 64, sDBC,
            p_whi + OFF_DTWF + (long)l * 512 * 32,
            p_whi + OFF_DTWB + (long)l * 512 * 32,
            mf_dtb + l * 512, mb_dtb + l * 512,
            p_delta, nullptr, nullptr, sDI, 512, nullptr, BL, 512, 32);
        // 8) selective scan -> yg hi/lo
        scan_kernel<<<256, 256>>>(mf_Al + l * 8192, mb_Al + l * 8192,
                                  mf_D + l * 512, mb_D + l * 512);
        // 9) out-proj + gate + concat (128x64 tile): cat[:, dir*512:] = (yg@ow^T)*silu(res)
        mma_gemm128<EPI_GATE,OUT_PAIR><<<dim3(8, MT128, 2), 256, SB_TOTAL>>>(
            p_yg_hi, p_yg_lo, 512, sDI,
            p_whi + OFF_OWF + (long)l * 512 * 512,
            p_whi + OFF_OWB + (long)l * 512 * 512,
            nullptr, nullptr, nullptr, p_cat_hi, p_cat_lo, 0, 1024, p_xcres, BL, 512, 512);
        // 10) block out-proj + residual (64 tile): h = cat @ out_w^T + h
        {
            f16* whi = p_whi + OFF_WOUT + (long)l * 256 * 1024;
            mma_gemm64<EPI_RESID,OUT_F32><<<dim3(4, MT64, 1), 256, S64_TOTAL>>>(
                p_cat_hi, p_cat_lo, 1024, 0, whi, whi, nullptr, nullptr,
                p_h, nullptr, nullptr, 0, 256, p_h, BL, DM, 1024);
        }
    }

    // final layernorm on cls rows -> output (4 x 256)
    ln_kernel<<<BATCH, DM>>>(p_h, fn_g, fn_b, (float*)d_out, nullptr, nullptr, SEQ);
}